// round 16
// baseline (speedup 1.0000x reference)
#include <cuda_runtime.h>
#include <math.h>

// AttFusion: out[g,c,s] = sum_m softmax_m(<x0,xm>_c / 16) * x[m,c,s]
// x: [28, 256, 8448] fp32; out: [8, 256, 8448] fp32.
//
// R16: 4-tile pipeline at R11's wave structure. Tile = 16 positions; CTA =
// (group, 64 positions = 4 tiles) -> grid 132 x 8 = 1056 CTAs @3/SM = 2.38
// waves (same as R11), but DRAM-read phases cover 4/5 of CTA lifetime
// (P1, M, M, M) vs R11's 2/3. Warp = 8 channel rows x 4 pos-quads (64B
// full-sector segments). __ldlu L2 reads, __stwt stores, per-warp softmax,
// double-buffered partials, one barrier per tile.

#define C_DIM   256
#define S_DIM   8448
#define N_MAX   5
#define NWARPS  8
#define TP      16              // positions per tile
#define NT      4               // tiles per CTA
#define NCH     4               // channel chunks per tile (8 rows/warp each)
#define FULL    0xffffffffu

__device__ __constant__ int c_off[8] = {0, 2, 5, 9, 14, 17, 19, 23};
__device__ __constant__ int c_len[8] = {2, 3, 4, 5, 3, 2, 4, 5};

template <int N>
__device__ __forceinline__ void reduce_store(
    float4* p, float (*red)[NWARPS][TP], int warp, int lo2, int rowg)
{
    // combine 8 channel rows: rowg occupies lane bits 2..4
#pragma unroll
    for (int m = 0; m < N; m++) {
#pragma unroll
        for (int d = 4; d <= 16; d <<= 1) {
            p[m].x += __shfl_down_sync(FULL, p[m].x, d);
            p[m].y += __shfl_down_sync(FULL, p[m].y, d);
            p[m].z += __shfl_down_sync(FULL, p[m].z, d);
            p[m].w += __shfl_down_sync(FULL, p[m].w, d);
        }
    }
    if (rowg == 0) {                     // lanes 0..3 hold quad sums
#pragma unroll
        for (int m = 0; m < N; m++)
            *reinterpret_cast<float4*>(&red[m][warp][lo2 * 4]) = p[m];
    }
}

// per-warp redundant softmax: lane&15 = position, broadcast to quad lanes
template <int N>
__device__ __forceinline__ void softmax_wv(
    const float (*red)[NWARPS][TP], int lane, int lo2, float4* wv)
{
    const int pos = lane & 15;
    float d[N];
#pragma unroll
    for (int m = 0; m < N; m++) {
        float a = 0.0f;
#pragma unroll
        for (int w = 0; w < NWARPS; w++) a += red[m][w][pos];
        d[m] = a * 0.0625f;              // 1/sqrt(256)
    }
    float mx = d[0];
#pragma unroll
    for (int m = 1; m < N; m++) mx = fmaxf(mx, d[m]);
    float wl[N], s = 0.0f;
#pragma unroll
    for (int m = 0; m < N; m++) { wl[m] = __expf(d[m] - mx); s += wl[m]; }
    const float inv = 1.0f / s;
#pragma unroll
    for (int m = 0; m < N; m++) {
        const float v = wl[m] * inv;     // lanes 0..15 hold positions 0..15
        wv[m].x = __shfl_sync(FULL, v, 4 * lo2 + 0);
        wv[m].y = __shfl_sync(FULL, v, 4 * lo2 + 1);
        wv[m].z = __shfl_sync(FULL, v, 4 * lo2 + 2);
        wv[m].w = __shfl_sync(FULL, v, 4 * lo2 + 3);
    }
}

template <int N>
__device__ __forceinline__ void run_group(
    const float* __restrict__ xg, float* __restrict__ og,
    float (*red0)[NWARPS][TP], float (*red1)[NWARPS][TP],
    int s0, int lane, int warp, int lo2, int rowg)
{
    const size_t mstr = (size_t)C_DIM * S_DIM;
    const size_t lpos = (size_t)(warp * 32 + rowg) * S_DIM + s0 + lo2 * 4;
    const float* xb = xg + lpos;             // tile t base = xb + TP*t
    float*       ob = og + lpos;

    float4 wv[N], pn[N];

    // ---- P1(t0): partial dots, 4 channel chunks (DRAM) ----
#pragma unroll
    for (int m = 0; m < N; m++) pn[m] = make_float4(0.f, 0.f, 0.f, 0.f);
    {
        const float* ptr = xb;
#pragma unroll
        for (int kk = 0; kk < NCH; kk++) {
            float4 xv[N];
#pragma unroll
            for (int m = 0; m < N; m++)
                xv[m] = *reinterpret_cast<const float4*>(ptr + m * mstr);
#pragma unroll
            for (int m = 0; m < N; m++) {
                pn[m].x += xv[0].x * xv[m].x;
                pn[m].y += xv[0].y * xv[m].y;
                pn[m].z += xv[0].z * xv[m].z;
                pn[m].w += xv[0].w * xv[m].w;
            }
            ptr += 8 * S_DIM;
        }
    }
    reduce_store<N>(pn, red0, warp, lo2, rowg);
    __syncthreads();

    // prefetch t1 chunk 0 (independent of softmax)
    float4 xn[N];
#pragma unroll
    for (int m = 0; m < N; m++)
        xn[m] = *reinterpret_cast<const float4*>(xb + TP + m * mstr);

    softmax_wv<N>(red0, lane, lo2, wv);

    // ---- 3 middle phases: P2(t) from L2 + P1(t+1) from DRAM ----
#pragma unroll
    for (int t = 0; t < NT - 1; t++) {
        const float* cp = xb + TP * t;
        const float* np = xb + TP * (t + 1);
        float*       op = ob + TP * t;

#pragma unroll
        for (int m = 0; m < N; m++) pn[m] = make_float4(0.f, 0.f, 0.f, 0.f);

#pragma unroll
        for (int kk = 0; kk < NCH; kk++) {
#pragma unroll
            for (int m = 0; m < N; m++) {
                pn[m].x += xn[0].x * xn[m].x;
                pn[m].y += xn[0].y * xn[m].y;
                pn[m].z += xn[0].z * xn[m].z;
                pn[m].w += xn[0].w * xn[m].w;
            }
            float4 xc[N];
#pragma unroll
            for (int m = 0; m < N; m++)
                xc[m] = __ldlu(reinterpret_cast<const float4*>(cp + m * mstr));
            float4 acc = make_float4(0.f, 0.f, 0.f, 0.f);
#pragma unroll
            for (int m = 0; m < N; m++) {
                acc.x += wv[m].x * xc[m].x;
                acc.y += wv[m].y * xc[m].y;
                acc.z += wv[m].z * xc[m].z;
                acc.w += wv[m].w * xc[m].w;
            }
            __stwt(reinterpret_cast<float4*>(op), acc);
            if (kk < NCH - 1) {
                np += 8 * S_DIM;
#pragma unroll
                for (int m = 0; m < N; m++)
                    xn[m] = *reinterpret_cast<const float4*>(np + m * mstr);
            }
            cp += 8 * S_DIM;
            op += 8 * S_DIM;
        }

        if (t & 1) {
            reduce_store<N>(pn, red0, warp, lo2, rowg);
            __syncthreads();
            // prefetch (t+2) chunk 0 before softmax, if another middle follows
            if (t + 2 < NT) {
#pragma unroll
                for (int m = 0; m < N; m++)
                    xn[m] = *reinterpret_cast<const float4*>(
                        xb + TP * (t + 2) + m * mstr);
            }
            softmax_wv<N>(red0, lane, lo2, wv);
        } else {
            reduce_store<N>(pn, red1, warp, lo2, rowg);
            __syncthreads();
            if (t + 2 < NT) {
#pragma unroll
                for (int m = 0; m < N; m++)
                    xn[m] = *reinterpret_cast<const float4*>(
                        xb + TP * (t + 2) + m * mstr);
            }
            softmax_wv<N>(red1, lane, lo2, wv);
        }
    }

    // ---- P2(t3): weighted sum from L2 ----
    {
        const float* ptr = xb + TP * (NT - 1);
        float* op = ob + TP * (NT - 1);
#pragma unroll
        for (int kk = 0; kk < NCH; kk++) {
            float4 xc[N];
#pragma unroll
            for (int m = 0; m < N; m++)
                xc[m] = __ldlu(reinterpret_cast<const float4*>(ptr + m * mstr));
            float4 acc = make_float4(0.f, 0.f, 0.f, 0.f);
#pragma unroll
            for (int m = 0; m < N; m++) {
                acc.x += wv[m].x * xc[m].x;
                acc.y += wv[m].y * xc[m].y;
                acc.z += wv[m].z * xc[m].z;
                acc.w += wv[m].w * xc[m].w;
            }
            __stwt(reinterpret_cast<float4*>(op), acc);
            ptr += 8 * S_DIM;
            op  += 8 * S_DIM;
        }
    }
}

__global__ __launch_bounds__(256, 3)
void attfusion_kernel(const float* __restrict__ x, float* __restrict__ out) {
    __shared__ float red0[N_MAX][NWARPS][TP];   // 2.5 KB
    __shared__ float red1[N_MAX][NWARPS][TP];   // 2.5 KB

    const int g    = blockIdx.y;                 // R11 grid order
    const int s0   = blockIdx.x * (TP * NT);     // 64 positions per CTA
    const int tid  = threadIdx.x;
    const int lane = tid & 31;
    const int warp = tid >> 5;
    const int lo2  = lane & 3;                   // position quad 0..3
    const int rowg = lane >> 2;                  // channel row 0..7

    const size_t mstr = (size_t)C_DIM * S_DIM;
    const float* xg = x + (size_t)c_off[g] * mstr;
    float*       og = out + (size_t)g * mstr;

    switch (c_len[g]) {
        case 2: run_group<2>(xg, og, red0, red1, s0, lane, warp, lo2, rowg); break;
        case 3: run_group<3>(xg, og, red0, red1, s0, lane, warp, lo2, rowg); break;
        case 4: run_group<4>(xg, og, red0, red1, s0, lane, warp, lo2, rowg); break;
        default: run_group<5>(xg, og, red0, red1, s0, lane, warp, lo2, rowg); break;
    }
}

extern "C" void kernel_launch(void* const* d_in, const int* in_sizes, int n_in,
                              void* d_out, int out_size) {
    const float* x = (const float*)d_in[0];
    float* out = (float*)d_out;

    dim3 grid(S_DIM / (TP * NT), 8);             // 132 x 8 = 1056 CTAs
    attfusion_kernel<<<grid, 256>>>(x, out);
}